// round 3
// baseline (speedup 1.0000x reference)
#include <cuda_runtime.h>
#include <math.h>

// ---------------------------------------------------------------------------
// AdaptivePatchEmbedding — B=128,C=32,S=336 -> N=4096, R=7, TARGET=6, D=512
// Straight-through gumbel == one-hot: compute only selected expert per region.
// Unique patch rows per region: P=8 ->6, P=16/24 ->2, P=48 ->1.
// Pipeline: pe_init(fp32) -> router (compaction) -> ONE persistent fused embed
// with all weight/pe reads through L1 (no smem staging; L1 stays warm inside
// the persistent kernel and LDS == L1-hit LDG bandwidth on sm_103a).
// ---------------------------------------------------------------------------

#define NREG 28672            // 4096 * 7
#define XP_ELEMS 88080384LL   // 4096 * 42 * 512

__device__ int   g_counts[4];
__device__ int   g_cursor[4];
__device__ int   g_lists[4 * NREG];
__device__ float g_pe[42 * 512];

// --------------------------- stage 0: pe table + counter reset --------------
__global__ void __launch_bounds__(256) pe_init_kernel() {
    int i = blockIdx.x * 256 + threadIdx.x;
    if (i < 4) { g_counts[i] = 0; g_cursor[i] = 0; }
    if (i < 42 * 512) {
        int pos = i >> 9;
        int d   = i & 511;
        // dv = 10000^(-(d&~1)/512) = 2^(-(d&~1) * log2(10000)/512)
        float dv  = exp2f((float)(d & ~1) * -2.5950645442958870e-2f);
        float ang = (float)pos * dv;
        g_pe[i] = (d & 1) ? cosf(ang) : sinf(ang);
    }
}

// --------------------------- stage 1: router --------------------------------
__global__ void __launch_bounds__(64) router_kernel(
    const float* __restrict__ x,  const float* __restrict__ un,
    const float* __restrict__ W1, const float* __restrict__ b1,
    const float* __restrict__ W2, const float* __restrict__ b2,
    float* __restrict__ out, int write_mode)
{
    __shared__ float W1s[48 * 64];
    __shared__ float W2s[256];
    __shared__ float b1s[64];
    int tid = threadIdx.x;
    for (int i = tid; i < 768; i += 64) ((float4*)W1s)[i] = ((const float4*)W1)[i];
    ((float4*)W2s)[tid] = ((const float4*)W2)[tid];
    b1s[tid] = b1[tid];
    __syncthreads();

    int region = blockIdx.x * 64 + tid;      // grid = 448 -> exactly 28672
    int n = region / 7, r = region - n * 7;

    float xr[48];
    const float4* xp = (const float4*)x + n * 84 + r * 12;
#pragma unroll
    for (int v = 0; v < 12; v++) {
        float4 t = xp[v];
        xr[4*v+0] = t.x; xr[4*v+1] = t.y; xr[4*v+2] = t.z; xr[4*v+3] = t.w;
    }

    float lg0 = b2[0], lg1 = b2[1], lg2 = b2[2], lg3 = b2[3];
#pragma unroll 2
    for (int k = 0; k < 64; k++) {
        float s = b1s[k];
#pragma unroll
        for (int j = 0; j < 48; j++) s = fmaf(xr[j], W1s[j * 64 + k], s);
        s = fmaxf(s, 0.0f);
        lg0 = fmaf(s, W2s[k*4+0], lg0);
        lg1 = fmaf(s, W2s[k*4+1], lg1);
        lg2 = fmaf(s, W2s[k*4+2], lg2);
        lg3 = fmaf(s, W2s[k*4+3], lg3);
    }

    const float* up = un + (long long)region * 4;
    float z0 = lg0 - logf(-logf(up[0] + 1e-10f) + 1e-10f);
    float z1 = lg1 - logf(-logf(up[1] + 1e-10f) + 1e-10f);
    float z2 = lg2 - logf(-logf(up[2] + 1e-10f) + 1e-10f);
    float z3 = lg3 - logf(-logf(up[3] + 1e-10f) + 1e-10f);

    int e = 0; float best = z0;              // first-max semantics like jnp.argmax
    if (z1 > best) { best = z1; e = 1; }
    if (z2 > best) { best = z2; e = 2; }
    if (z3 > best) { best = z3; e = 3; }

    int slot = atomicAdd(&g_counts[e], 1);
    g_lists[e * NREG + slot] = region;

    if (write_mode >= 2) out[XP_ELEMS + 1 + (long long)r * 4096 + n] = (float)e;
    if (write_mode >= 1 && region == 0) out[XP_ELEMS] = 32.0f;
}

// --------------------------- stage 2: persistent fused embed ----------------
// 12 unique rows per chunk; thread (tx in [0,128), ty in {0,1}) owns 6 rows x 4
// cols. For P: K = 7-48/P repeats per unique row, U = ceil(6/K) unique
// rows/region, RPB = 12/U regions per chunk. Work via per-expert atomic
// cursors. W and pe read through L1 (warm across chunks in the persistent
// kernel); only the 12 xr rows + worklist live in smem.
template<int P>
__device__ __forceinline__ void embed_expert(
    const float4* __restrict__ x4, const float4* __restrict__ W4,
    float4* __restrict__ out4, float* xrs, int* ibuf)
{
    constexpr int E   = (P == 8) ? 0 : (P == 16) ? 1 : (P == 24) ? 2 : 3;
    constexpr int K   = 7 - 48 / P;
    constexpr int U   = (6 + K - 1) / K;
    constexpr int RPB = 12 / U;

    const int tid = threadIdx.x;
    const int cnt = g_counts[E];
    const int tx = tid & 127, ty = tid >> 7;

    int aoff[6];
#pragma unroll
    for (int rr = 0; rr < 6; rr++) {
        int row = ty * 6 + rr;
        aoff[rr] = (row / U) * 48 + (row % U) * P;
    }

    for (;;) {
        if (tid == 0) ibuf[15] = atomicAdd(&g_cursor[E], 1);
        __syncthreads();
        int base = ibuf[15] * RPB;
        if (base >= cnt) break;
        int nval = min(RPB, cnt - base);
        if (tid < nval) ibuf[tid] = g_lists[E * NREG + base + tid];
        __syncthreads();

        for (int i = tid; i < nval * 12; i += 256) {
            int reg = i / 12, v = i - reg * 12;
            int rid = ibuf[reg];
            int n = rid / 7, r = rid - n * 7;
            ((float4*)xrs)[reg * 12 + v] = __ldg(&x4[n * 84 + r * 12 + v]);
        }
        __syncthreads();

        float4 acc[6];
#pragma unroll
        for (int i = 0; i < 6; i++) acc[i] = make_float4(0.f, 0.f, 0.f, 0.f);

#pragma unroll
        for (int k = 0; k < P; k += 2) {
            float4 b0 = __ldg(&W4[k * 128 + tx]);
            float4 b1 = __ldg(&W4[(k + 1) * 128 + tx]);
#pragma unroll
            for (int rr = 0; rr < 6; rr++) {
                float2 a = *(const float2*)&xrs[aoff[rr] + k];
                acc[rr].x = fmaf(a.x, b0.x, acc[rr].x);
                acc[rr].y = fmaf(a.x, b0.y, acc[rr].y);
                acc[rr].z = fmaf(a.x, b0.z, acc[rr].z);
                acc[rr].w = fmaf(a.x, b0.w, acc[rr].w);
                acc[rr].x = fmaf(a.y, b1.x, acc[rr].x);
                acc[rr].y = fmaf(a.y, b1.y, acc[rr].y);
                acc[rr].z = fmaf(a.y, b1.z, acc[rr].z);
                acc[rr].w = fmaf(a.y, b1.w, acc[rr].w);
            }
        }

        const float4* pe4 = (const float4*)g_pe;
#pragma unroll
        for (int rr = 0; rr < 6; rr++) {
            int row = ty * 6 + rr;
            int reg = row / U;
            int q   = row % U;
            if (reg >= nval) continue;
            int rid = ibuf[reg];
            int n = rid / 7, r = rid - n * 7;
#pragma unroll
            for (int t = q * K; t < ((q + 1) * K < 6 ? (q + 1) * K : 6); t++) {
                int pos = r * 6 + t;
                float4 p = __ldg(&pe4[pos * 128 + tx]);
                float4 v = make_float4(acc[rr].x + p.x, acc[rr].y + p.y,
                                       acc[rr].z + p.z, acc[rr].w + p.w);
                __stcs(&out4[(long long)n * 5376 + pos * 128 + tx], v);
            }
        }
        __syncthreads();
    }
    __syncthreads();   // all threads done with ibuf before next expert reuses it
}

__global__ void __launch_bounds__(256, 5) embed_fused_kernel(
    const float4* __restrict__ x4,
    const float4* __restrict__ We0, const float4* __restrict__ We1,
    const float4* __restrict__ We2, const float4* __restrict__ We3,
    float4* __restrict__ out4)
{
    __shared__ float xrs[12 * 48];
    __shared__ int   ibuf[16];

    embed_expert<48>(x4, We3, out4, xrs, ibuf);
    embed_expert<24>(x4, We2, out4, xrs, ibuf);
    embed_expert<16>(x4, We1, out4, xrs, ibuf);
    embed_expert< 8>(x4, We0, out4, xrs, ibuf);
}

// --------------------------- launch ------------------------------------------
extern "C" void kernel_launch(void* const* d_in, const int* in_sizes, int n_in,
                              void* d_out, int out_size) {
    const float* x  = (const float*)d_in[0];
    const float* un = (const float*)d_in[1];
    const float* W1 = (const float*)d_in[2];
    const float* b1 = (const float*)d_in[3];
    const float* W2 = (const float*)d_in[4];
    const float* b2 = (const float*)d_in[5];
    const float4* We0 = (const float4*)d_in[6];
    const float4* We1 = (const float4*)d_in[7];
    const float4* We2 = (const float4*)d_in[8];
    const float4* We3 = (const float4*)d_in[9];
    float*  out  = (float*)d_out;
    float4* out4 = (float4*)d_out;
    const float4* x4 = (const float4*)d_in[0];

    int write_mode = 0;
    if ((long long)out_size >= XP_ELEMS + 1 + 28672) write_mode = 2;
    else if ((long long)out_size >= XP_ELEMS + 1)    write_mode = 1;

    pe_init_kernel<<<84, 256>>>();
    router_kernel<<<448, 64>>>(x, un, W1, b1, W2, b2, out, write_mode);
    embed_fused_kernel<<<740, 256>>>(x4, We0, We1, We2, We3, out4);
    (void)in_sizes; (void)n_in;
}

// round 4
// speedup vs baseline: 1.5301x; 1.5301x over previous
#include <cuda_runtime.h>
#include <math.h>

// ---------------------------------------------------------------------------
// AdaptivePatchEmbedding — B=128,C=32,S=336 -> N=4096, R=7, TARGET=6, D=512
// Straight-through gumbel == one-hot: compute only selected expert per region.
// Unique patch rows per region: P=8 ->6, P=16/24 ->2, P=48 ->1.
// pe_init(fp64 dv, one exp per dim-pair) -> router (compaction) ->
// persistent fused embed with a UNIFIED chunk cursor across experts
// (blocks stay within one expert's W table; smem-staged weights).
// ---------------------------------------------------------------------------

#define NREG 28672            // 4096 * 7
#define XP_ELEMS 88080384LL   // 4096 * 42 * 512

__device__ int   g_counts[4];
__device__ int   g_ucur;
__device__ int   g_lists[4 * NREG];
__device__ float g_pe[42 * 512];

// --------------------------- stage 0: pe table + counter reset --------------
// grid 42 (one block per pos), block 256 (one thread per dim-pair).
__global__ void __launch_bounds__(256) pe_init_kernel() {
    int pos = blockIdx.x, t = threadIdx.x;
    if (pos == 0 && t < 5) { if (t < 4) g_counts[t] = 0; else g_ucur = 0; }
    double dv  = exp((double)(2 * t) * -(log(10000.0) / 512.0));
    float ang  = (float)((double)pos * dv);
    float2 sc  = make_float2(sinf(ang), cosf(ang));
    *(float2*)&g_pe[pos * 512 + 2 * t] = sc;
}

// --------------------------- stage 1: router --------------------------------
__global__ void __launch_bounds__(64) router_kernel(
    const float* __restrict__ x,  const float* __restrict__ un,
    const float* __restrict__ W1, const float* __restrict__ b1,
    const float* __restrict__ W2, const float* __restrict__ b2,
    float* __restrict__ out, int write_mode)
{
    __shared__ float W1s[48 * 64];
    __shared__ float W2s[256];
    __shared__ float b1s[64];
    int tid = threadIdx.x;
    for (int i = tid; i < 768; i += 64) ((float4*)W1s)[i] = ((const float4*)W1)[i];
    ((float4*)W2s)[tid] = ((const float4*)W2)[tid];
    b1s[tid] = b1[tid];
    __syncthreads();

    int region = blockIdx.x * 64 + tid;      // grid = 448 -> exactly 28672
    int n = region / 7, r = region - n * 7;

    float xr[48];
    const float4* xp = (const float4*)x + n * 84 + r * 12;
#pragma unroll
    for (int v = 0; v < 12; v++) {
        float4 t4 = xp[v];
        xr[4*v+0] = t4.x; xr[4*v+1] = t4.y; xr[4*v+2] = t4.z; xr[4*v+3] = t4.w;
    }

    float lg0 = b2[0], lg1 = b2[1], lg2 = b2[2], lg3 = b2[3];
#pragma unroll 2
    for (int k = 0; k < 64; k++) {
        float s = b1s[k];
#pragma unroll
        for (int j = 0; j < 48; j++) s = fmaf(xr[j], W1s[j * 64 + k], s);
        s = fmaxf(s, 0.0f);
        lg0 = fmaf(s, W2s[k*4+0], lg0);
        lg1 = fmaf(s, W2s[k*4+1], lg1);
        lg2 = fmaf(s, W2s[k*4+2], lg2);
        lg3 = fmaf(s, W2s[k*4+3], lg3);
    }

    const float* up = un + (long long)region * 4;
    float z0 = lg0 - logf(-logf(up[0] + 1e-10f) + 1e-10f);
    float z1 = lg1 - logf(-logf(up[1] + 1e-10f) + 1e-10f);
    float z2 = lg2 - logf(-logf(up[2] + 1e-10f) + 1e-10f);
    float z3 = lg3 - logf(-logf(up[3] + 1e-10f) + 1e-10f);

    int e = 0; float best = z0;              // first-max semantics like jnp.argmax
    if (z1 > best) { best = z1; e = 1; }
    if (z2 > best) { best = z2; e = 2; }
    if (z3 > best) { best = z3; e = 3; }

    int slot = atomicAdd(&g_counts[e], 1);
    g_lists[e * NREG + slot] = region;

    if (write_mode >= 2) out[XP_ELEMS + 1 + (long long)r * 4096 + n] = (float)e;
    if (write_mode >= 1 && region == 0) out[XP_ELEMS] = 32.0f;
}

// --------------------------- stage 2: persistent fused embed ----------------
// Chunk = 12 unique rows (RPB regions) x 512 cols. Thread (tx in [0,128),
// ty in {0,1}) owns 6 rows x 4 cols. K = 7-48/P repeats, U = ceil(6/K) unique
// rows/region, RPB = 12/U. Chunks of all experts share one global cursor;
// W staged to smem (<=24 rows; P=48 upper half via L1 __ldg).

template<int P>
__device__ __forceinline__ void stage_w(const float4* __restrict__ W4,
                                        float4* Wsm4) {
    constexpr int SR = (P < 24) ? P : 24;
    for (int i = threadIdx.x; i < SR * 128; i += 256) Wsm4[i] = W4[i];
}

template<int P>
__device__ __forceinline__ void do_chunk(
    int base, int cnt,
    const float4* __restrict__ x4, const float4* __restrict__ W4,
    float4* __restrict__ out4, const float4* Wsm4, float* xrs)
{
    constexpr int E   = (P == 8) ? 0 : (P == 16) ? 1 : (P == 24) ? 2 : 3;
    constexpr int K   = 7 - 48 / P;
    constexpr int U   = (6 + K - 1) / K;
    constexpr int RPB = 12 / U;
    constexpr int SR  = (P < 24) ? P : 24;

    const int tid = threadIdx.x;
    const int tx  = tid & 127, ty = tid >> 7;
    const int nval = min(RPB, cnt - base);
    const int* lst = g_lists + E * NREG + base;

    for (int i = tid; i < nval * 12; i += 256) {
        int reg = i / 12, v = i - reg * 12;
        int rid = __ldg(&lst[reg]);
        int n = rid / 7, r = rid - n * 7;
        ((float4*)xrs)[reg * 12 + v] = __ldg(&x4[n * 84 + r * 12 + v]);
    }
    __syncthreads();

    int aoff[6];
#pragma unroll
    for (int rr = 0; rr < 6; rr++) {
        int row = ty * 6 + rr;
        aoff[rr] = (row / U) * 48 + (row % U) * P;
    }

    float4 acc[6];
#pragma unroll
    for (int i = 0; i < 6; i++) acc[i] = make_float4(0.f, 0.f, 0.f, 0.f);

#pragma unroll
    for (int k = 0; k < P; k += 4) {
        float4 b0, b1, b2, b3;
        if (k < SR) {
            b0 = Wsm4[(k + 0) * 128 + tx];
            b1 = Wsm4[(k + 1) * 128 + tx];
            b2 = Wsm4[(k + 2) * 128 + tx];
            b3 = Wsm4[(k + 3) * 128 + tx];
        } else {
            b0 = __ldg(&W4[(k + 0) * 128 + tx]);
            b1 = __ldg(&W4[(k + 1) * 128 + tx]);
            b2 = __ldg(&W4[(k + 2) * 128 + tx]);
            b3 = __ldg(&W4[(k + 3) * 128 + tx]);
        }
#pragma unroll
        for (int rr = 0; rr < 6; rr++) {
            float4 a = *(const float4*)&xrs[aoff[rr] + k];
            acc[rr].x = fmaf(a.x, b0.x, acc[rr].x);
            acc[rr].y = fmaf(a.x, b0.y, acc[rr].y);
            acc[rr].z = fmaf(a.x, b0.z, acc[rr].z);
            acc[rr].w = fmaf(a.x, b0.w, acc[rr].w);
            acc[rr].x = fmaf(a.y, b1.x, acc[rr].x);
            acc[rr].y = fmaf(a.y, b1.y, acc[rr].y);
            acc[rr].z = fmaf(a.y, b1.z, acc[rr].z);
            acc[rr].w = fmaf(a.y, b1.w, acc[rr].w);
            acc[rr].x = fmaf(a.z, b2.x, acc[rr].x);
            acc[rr].y = fmaf(a.z, b2.y, acc[rr].y);
            acc[rr].z = fmaf(a.z, b2.z, acc[rr].z);
            acc[rr].w = fmaf(a.z, b2.w, acc[rr].w);
            acc[rr].x = fmaf(a.w, b3.x, acc[rr].x);
            acc[rr].y = fmaf(a.w, b3.y, acc[rr].y);
            acc[rr].z = fmaf(a.w, b3.z, acc[rr].z);
            acc[rr].w = fmaf(a.w, b3.w, acc[rr].w);
        }
    }

    const float4* pe4 = (const float4*)g_pe;
#pragma unroll
    for (int rr = 0; rr < 6; rr++) {
        int row = ty * 6 + rr;
        int reg = row / U;
        int q   = row % U;
        if (reg >= nval) continue;
        int rid = __ldg(&lst[reg]);
        int n = rid / 7, r = rid - n * 7;
#pragma unroll
        for (int t = q * K; t < ((q + 1) * K < 6 ? (q + 1) * K : 6); t++) {
            int pos = r * 6 + t;
            float4 p = __ldg(&pe4[pos * 128 + tx]);
            float4 v = make_float4(acc[rr].x + p.x, acc[rr].y + p.y,
                                   acc[rr].z + p.z, acc[rr].w + p.w);
            __stcs(&out4[(long long)n * 5376 + pos * 128 + tx], v);
        }
    }
}

__global__ void __launch_bounds__(256, 4) embed_fused_kernel(
    const float4* __restrict__ x4,
    const float4* __restrict__ We0, const float4* __restrict__ We1,
    const float4* __restrict__ We2, const float4* __restrict__ We3,
    float4* __restrict__ out4)
{
    extern __shared__ float sm[];
    float4* Wsm4 = (float4*)sm;            // 24*512 floats
    float*  xrs  = sm + 24 * 512;          // 12*48 floats
    __shared__ int sgrab;

    const int tid = threadIdx.x;

    // unified chunk index space: expert order 0,1,2,3; RPB = {2,6,6,12}
    int c0 = g_counts[0], c1 = g_counts[1], c2 = g_counts[2], c3 = g_counts[3];
    int ch0 = (c0 + 1) / 2, ch1 = (c1 + 5) / 6, ch2 = (c2 + 5) / 6, ch3 = (c3 + 11) / 12;
    int o1 = ch0, o2 = o1 + ch1, o3 = o2 + ch2, T = o3 + ch3;

    const float4* Wtab[4] = { We0, We1, We2, We3 };
    int cur_e = -1;

    for (;;) {
        if (tid == 0) sgrab = atomicAdd(&g_ucur, 1);
        __syncthreads();                    // also fences previous chunk's smem use
        int c = sgrab;
        if (c >= T) break;

        int e, rel;
        if      (c < o1) { e = 0; rel = c; }
        else if (c < o2) { e = 1; rel = c - o1; }
        else if (c < o3) { e = 2; rel = c - o2; }
        else             { e = 3; rel = c - o3; }

        if (e != cur_e) {
            switch (e) {
                case 0: stage_w< 8>(Wtab[0], Wsm4); break;
                case 1: stage_w<16>(Wtab[1], Wsm4); break;
                case 2: stage_w<24>(Wtab[2], Wsm4); break;
                case 3: stage_w<48>(Wtab[3], Wsm4); break;
            }
            cur_e = e;
        }

        switch (e) {
            case 0: do_chunk< 8>(rel *  2, c0, x4, Wtab[0], out4, Wsm4, xrs); break;
            case 1: do_chunk<16>(rel *  6, c1, x4, Wtab[1], out4, Wsm4, xrs); break;
            case 2: do_chunk<24>(rel *  6, c2, x4, Wtab[2], out4, Wsm4, xrs); break;
            case 3: do_chunk<48>(rel * 12, c3, x4, Wtab[3], out4, Wsm4, xrs); break;
        }
    }
}

// --------------------------- launch ------------------------------------------
extern "C" void kernel_launch(void* const* d_in, const int* in_sizes, int n_in,
                              void* d_out, int out_size) {
    const float* x  = (const float*)d_in[0];
    const float* un = (const float*)d_in[1];
    const float* W1 = (const float*)d_in[2];
    const float* b1 = (const float*)d_in[3];
    const float* W2 = (const float*)d_in[4];
    const float* b2 = (const float*)d_in[5];
    const float4* We0 = (const float4*)d_in[6];
    const float4* We1 = (const float4*)d_in[7];
    const float4* We2 = (const float4*)d_in[8];
    const float4* We3 = (const float4*)d_in[9];
    float*  out  = (float*)d_out;
    float4* out4 = (float4*)d_out;
    const float4* x4 = (const float4*)d_in[0];

    int write_mode = 0;
    if ((long long)out_size >= XP_ELEMS + 1 + 28672) write_mode = 2;
    else if ((long long)out_size >= XP_ELEMS + 1)    write_mode = 1;

    const int SMEM = (24 * 512 + 12 * 48) * 4;   // 51456 bytes
    cudaFuncSetAttribute(embed_fused_kernel,
                         cudaFuncAttributeMaxDynamicSharedMemorySize, SMEM);

    pe_init_kernel<<<42, 256>>>();
    router_kernel<<<448, 64>>>(x, un, W1, b1, W2, b2, out, write_mode);
    embed_fused_kernel<<<592, 256, SMEM>>>(x4, We0, We1, We2, We3, out4);
    (void)in_sizes; (void)n_in;
}

// round 5
// speedup vs baseline: 1.7170x; 1.1222x over previous
#include <cuda_runtime.h>
#include <math.h>

// ---------------------------------------------------------------------------
// AdaptivePatchEmbedding — B=128,C=32,S=336 -> N=4096, R=7, TARGET=6, D=512
// Straight-through gumbel == one-hot: compute only selected expert per region.
// Unique patch rows per region: P=8 ->6, P=16/24 ->2, P=48 ->1.
// TWO launches: router (also builds pe table + expert compaction) ->
// persistent fused embed (R2-proven structure; last block resets counters).
// ---------------------------------------------------------------------------

#define NREG 28672            // 4096 * 7
#define XP_ELEMS 88080384LL   // 4096 * 42 * 512

__device__ int   g_counts[4];   // zero at module load; embed resets at end
__device__ int   g_cursor[4];
__device__ int   g_done;
__device__ int   g_lists[4 * NREG];
__device__ float g_pe[42 * 512];

// --------------------------- stage 1: router + pe table ---------------------
__global__ void __launch_bounds__(64) router_kernel(
    const float* __restrict__ x,  const float* __restrict__ un,
    const float* __restrict__ W1, const float* __restrict__ b1,
    const float* __restrict__ W2, const float* __restrict__ b2,
    float* __restrict__ out, int write_mode)
{
    __shared__ float W1s[48 * 64];
    __shared__ float W2s[256];
    __shared__ float b1s[64];
    int tid = threadIdx.x;
    int region = blockIdx.x * 64 + tid;      // grid = 448 -> exactly 28672

    // ---- positional-embedding table: one dim-pair per thread, first 10752
    // threads. Issued first so the fp64 exp latency hides under the MLP.
    if (region < 10752) {
        int pos = region >> 8;               // [0,42)
        int tp  = region & 255;              // dim pair [0,256)
        double dv = exp((double)(2 * tp) * -(log(10000.0) / 512.0));
        float ang = (float)((double)pos * dv);
        float2 sc = make_float2(sinf(ang), cosf(ang));
        *(float2*)&g_pe[pos * 512 + 2 * tp] = sc;
    }

    for (int i = tid; i < 768; i += 64) ((float4*)W1s)[i] = ((const float4*)W1)[i];
    ((float4*)W2s)[tid] = ((const float4*)W2)[tid];
    b1s[tid] = b1[tid];
    __syncthreads();

    int n = region / 7, r = region - n * 7;

    float xr[48];
    const float4* xp = (const float4*)x + n * 84 + r * 12;
#pragma unroll
    for (int v = 0; v < 12; v++) {
        float4 t4 = xp[v];
        xr[4*v+0] = t4.x; xr[4*v+1] = t4.y; xr[4*v+2] = t4.z; xr[4*v+3] = t4.w;
    }

    float lg0 = b2[0], lg1 = b2[1], lg2 = b2[2], lg3 = b2[3];
#pragma unroll 2
    for (int k = 0; k < 64; k++) {
        float s = b1s[k];
#pragma unroll
        for (int j = 0; j < 48; j++) s = fmaf(xr[j], W1s[j * 64 + k], s);
        s = fmaxf(s, 0.0f);
        lg0 = fmaf(s, W2s[k*4+0], lg0);
        lg1 = fmaf(s, W2s[k*4+1], lg1);
        lg2 = fmaf(s, W2s[k*4+2], lg2);
        lg3 = fmaf(s, W2s[k*4+3], lg3);
    }

    const float* up = un + (long long)region * 4;
    float z0 = lg0 - logf(-logf(up[0] + 1e-10f) + 1e-10f);
    float z1 = lg1 - logf(-logf(up[1] + 1e-10f) + 1e-10f);
    float z2 = lg2 - logf(-logf(up[2] + 1e-10f) + 1e-10f);
    float z3 = lg3 - logf(-logf(up[3] + 1e-10f) + 1e-10f);

    int e = 0; float best = z0;              // first-max semantics like jnp.argmax
    if (z1 > best) { best = z1; e = 1; }
    if (z2 > best) { best = z2; e = 2; }
    if (z3 > best) { best = z3; e = 3; }

    int slot = atomicAdd(&g_counts[e], 1);
    g_lists[e * NREG + slot] = region;

    if (write_mode >= 2) out[XP_ELEMS + 1 + (long long)r * 4096 + n] = (float)e;
    if (write_mode >= 1 && region == 0) out[XP_ELEMS] = 32.0f;
}

// --------------------------- stage 2: persistent fused embed ----------------
// 12 unique rows per chunk; thread (tx in [0,128), ty in {0,1}) owns 6 rows x 4
// cols. For P: K = 7-48/P repeats per unique row, U = ceil(6/K) unique
// rows/region, RPB = 12/U regions per chunk. Per-expert atomic cursors.
template<int P, bool WSM>
__device__ __forceinline__ void embed_expert(
    const float4* __restrict__ x4, const float4* __restrict__ W4,
    float4* __restrict__ out4, float* Wsm, float* xrs, int* ibuf)
{
    constexpr int E   = (P == 8) ? 0 : (P == 16) ? 1 : (P == 24) ? 2 : 3;
    constexpr int K   = 7 - 48 / P;
    constexpr int U   = (6 + K - 1) / K;
    constexpr int RPB = 12 / U;

    const int tid = threadIdx.x;
    const int cnt = g_counts[E];

    if (WSM) {
        for (int i = tid; i < P * 128; i += 256)
            ((float4*)Wsm)[i] = W4[i];
    }
    const int tx = tid & 127, ty = tid >> 7;

    int aoff[6];
#pragma unroll
    for (int rr = 0; rr < 6; rr++) {
        int row = ty * 6 + rr;
        aoff[rr] = (row / U) * 48 + (row % U) * P;
    }

    for (;;) {
        if (tid == 0) ibuf[15] = atomicAdd(&g_cursor[E], 1);
        __syncthreads();
        int base = ibuf[15] * RPB;
        if (base >= cnt) break;
        int nval = min(RPB, cnt - base);
        if (tid < nval) ibuf[tid] = g_lists[E * NREG + base + tid];
        __syncthreads();

        for (int i = tid; i < nval * 12; i += 256) {
            int reg = i / 12, v = i - reg * 12;
            int rid = ibuf[reg];
            int n = rid / 7, r = rid - n * 7;
            ((float4*)xrs)[reg * 12 + v] = __ldg(&x4[n * 84 + r * 12 + v]);
        }
        __syncthreads();

        float4 acc[6];
#pragma unroll
        for (int i = 0; i < 6; i++) acc[i] = make_float4(0.f, 0.f, 0.f, 0.f);

#pragma unroll
        for (int k = 0; k < P; k += 2) {
            float4 b0 = WSM ? ((const float4*)Wsm)[k * 128 + tx]
                            : __ldg(&W4[k * 128 + tx]);
            float4 b1 = WSM ? ((const float4*)Wsm)[(k + 1) * 128 + tx]
                            : __ldg(&W4[(k + 1) * 128 + tx]);
#pragma unroll
            for (int rr = 0; rr < 6; rr++) {
                float2 a = *(const float2*)&xrs[aoff[rr] + k];
                acc[rr].x = fmaf(a.x, b0.x, acc[rr].x);
                acc[rr].y = fmaf(a.x, b0.y, acc[rr].y);
                acc[rr].z = fmaf(a.x, b0.z, acc[rr].z);
                acc[rr].w = fmaf(a.x, b0.w, acc[rr].w);
                acc[rr].x = fmaf(a.y, b1.x, acc[rr].x);
                acc[rr].y = fmaf(a.y, b1.y, acc[rr].y);
                acc[rr].z = fmaf(a.y, b1.z, acc[rr].z);
                acc[rr].w = fmaf(a.y, b1.w, acc[rr].w);
            }
        }

        const float4* pe4 = (const float4*)g_pe;
#pragma unroll
        for (int rr = 0; rr < 6; rr++) {
            int row = ty * 6 + rr;
            int reg = row / U;
            int q   = row % U;
            if (reg >= nval) continue;
            int rid = ibuf[reg];
            int n = rid / 7, r = rid - n * 7;
#pragma unroll
            for (int t = q * K; t < ((q + 1) * K < 6 ? (q + 1) * K : 6); t++) {
                int pos = r * 6 + t;
                float4 p = __ldg(&pe4[pos * 128 + tx]);
                float4 v = make_float4(acc[rr].x + p.x, acc[rr].y + p.y,
                                       acc[rr].z + p.z, acc[rr].w + p.w);
                __stcs(&out4[(long long)n * 5376 + pos * 128 + tx], v);
            }
        }
        __syncthreads();
    }
    __syncthreads();   // all threads done with ibuf before next expert reuses it
}

__global__ void __launch_bounds__(256, 4) embed_fused_kernel(
    const float4* __restrict__ x4,
    const float4* __restrict__ We0, const float4* __restrict__ We1,
    const float4* __restrict__ We2, const float4* __restrict__ We3,
    float4* __restrict__ out4)
{
    extern __shared__ float sm[];
    float* Wsm = sm;                       // up to 24*512 floats
    float* xrs = sm + 24 * 512;            // 12*48 floats
    int*   ibuf = (int*)(xrs + 12 * 48);   // 16 ints

    embed_expert<48, false>(x4, We3, out4, Wsm, xrs, ibuf);
    embed_expert<24, true >(x4, We2, out4, Wsm, xrs, ibuf);
    embed_expert<16, true >(x4, We1, out4, Wsm, xrs, ibuf);
    embed_expert< 8, true >(x4, We0, out4, Wsm, xrs, ibuf);

    // last block out resets routing state for the next graph replay
    if (threadIdx.x == 0) {
        int d = atomicAdd(&g_done, 1);
        if (d == (int)gridDim.x - 1) {
            g_counts[0] = 0; g_counts[1] = 0; g_counts[2] = 0; g_counts[3] = 0;
            g_cursor[0] = 0; g_cursor[1] = 0; g_cursor[2] = 0; g_cursor[3] = 0;
            g_done = 0;
        }
    }
}

// --------------------------- launch ------------------------------------------
extern "C" void kernel_launch(void* const* d_in, const int* in_sizes, int n_in,
                              void* d_out, int out_size) {
    const float* x  = (const float*)d_in[0];
    const float* un = (const float*)d_in[1];
    const float* W1 = (const float*)d_in[2];
    const float* b1 = (const float*)d_in[3];
    const float* W2 = (const float*)d_in[4];
    const float* b2 = (const float*)d_in[5];
    const float4* We0 = (const float4*)d_in[6];
    const float4* We1 = (const float4*)d_in[7];
    const float4* We2 = (const float4*)d_in[8];
    const float4* We3 = (const float4*)d_in[9];
    float*  out  = (float*)d_out;
    float4* out4 = (float4*)d_out;
    const float4* x4 = (const float4*)d_in[0];

    int write_mode = 0;
    if ((long long)out_size >= XP_ELEMS + 1 + 28672) write_mode = 2;
    else if ((long long)out_size >= XP_ELEMS + 1)    write_mode = 1;

    const int SMEM = (24 * 512 + 12 * 48) * 4 + 64;   // 51520 bytes
    cudaFuncSetAttribute(embed_fused_kernel,
                         cudaFuncAttributeMaxDynamicSharedMemorySize, SMEM);

    router_kernel<<<448, 64>>>(x, un, W1, b1, W2, b2, out, write_mode);
    embed_fused_kernel<<<592, 256, SMEM>>>(x4, We0, We1, We2, We3, out4);
    (void)in_sizes; (void)n_in;
}